// round 12
// baseline (speedup 1.0000x reference)
#include <cuda_runtime.h>
#include <stdint.h>

#define HH 721
#define WW 1440
#define NPTS (HH*WW)
#define NQ4  (NPTS/4)
#define BB 16
#define CC 4
#define DD 256
#define NV 12
#define NCHUNK 6
#define CHW 240            // 6*240 = 1440
#define GNN_BLOCKS 32
#define PI_D 3.141592653589793
#define TWOPI_D (2.0*PI_D)

static __device__ double        g_dla2d[NV][HH];
static __device__ double        g_dlo2d[NV][WW];
static __device__ float         g_dla2f[NV][HH];
static __device__ float         g_dlo2f[NV][WW];
static __device__ float         g_cmin[NV][NCHUNK];   // chunk min of dlo2f
static __device__ float         g_cmax[NV][NCHUNK];   // chunk max of dlo2f
static __device__ unsigned int  g_v2gi[NV];
static __device__ unsigned char g_vmap[NPTS];
static __device__ float         g_nodes[BB*NV*CC];
static __device__ float         g_hn[BB*NV*DD];
static __device__ unsigned int  g_bar;

__constant__ signed char c_vcode[NV][3] = {
    {-1,2,0},{1,2,0},{-1,-2,0},{1,-2,0},{0,-1,2},{0,1,2},
    {0,-1,-2},{0,1,-2},{2,0,-1},{2,0,1},{-2,0,-1},{-2,0,1}};
__constant__ int c_nbr[NV][5] = {
    {11,5,1,7,10},{0,5,7,9,8},{11,10,3,4,6},{9,4,2,6,8},
    {5,11,3,9,2},{0,11,1,9,4},{10,7,3,2,8},{0,1,10,6,8},
    {7,1,3,6,9},{1,5,3,4,8},{0,7,11,2,6},{0,5,10,2,4}};

// ---- K0: per-vertex f64 tables + chunk min/max + separable argmin; resets barrier ----
__global__ void __launch_bounds__(256) k_prep() {
    int v = blockIdx.x;
    int t = threadIdx.x;
    if (v == 0 && t == 0) g_bar = 0u;

    __shared__ double svlat, svlon;
    __shared__ double rv[8];
    __shared__ int    ri[8];
    __shared__ int    sbest[2];

    if (t == 0) {
        float phi = (float)((1.0 + sqrt(5.0)) * 0.5);
        float c[3];
#pragma unroll
        for (int k = 0; k < 3; k++) {
            int cd = c_vcode[v][k];
            float m = (cd == 2 || cd == -2) ? phi : 1.0f;
            c[k] = (cd == 0) ? 0.0f : (cd < 0 ? -m : m);
        }
        float n2 = __fadd_rn(__fadd_rn(__fmul_rn(c[0],c[0]), __fmul_rn(c[1],c[1])),
                             __fmul_rn(c[2],c[2]));
        float nrm = __fsqrt_rn(n2);
        float x = __fdiv_rn(c[0],nrm), y = __fdiv_rn(c[1],nrm), z = __fdiv_rn(c[2],nrm);
        float s = __fsqrt_rn(__fsub_rn(1.0f, __fmul_rn(z,z)));
        svlat = (double)__fmul_rn(2.0f, atan2f(z, __fadd_rn(1.0f, s)));   // XLA asin
        svlon = (double)atan2f(y, x);
    }
    __syncthreads();
    double vlat = svlat, vlon = svlon;

    double bla = 1.0e300, blo = 1.0e300; int bia = 0, bio = 0;
    double dla_s = __ddiv_rn(PI_D, 720.0);
    double dlo_s = __ddiv_rn(TWOPI_D, 1439.0);
    for (int li = t; li < HH; li += 256) {
        double lat = __dadd_rn(-(PI_D*0.5), __dmul_rn((double)li, dla_s));
        if (li == 360) lat = 1.0e-12;            // symmetry row pinned positive (validated)
        double dla = __dsub_rn(lat, vlat);
        double q = __dmul_rn(dla, dla);
        g_dla2d[v][li] = q;
        g_dla2f[v][li] = (float)q;
        if (q < bla) { bla = q; bia = li; }
    }
    for (int lj = t; lj < WW; lj += 256) {
        double lon = __dadd_rn(-PI_D, __dmul_rn((double)lj, dlo_s));
        double raw = __dadd_rn(__dsub_rn(lon, vlon), PI_D);
        double r = raw;
        if (raw >= TWOPI_D)   r = __dsub_rn(raw, TWOPI_D);
        else if (raw < 0.0)   r = __dadd_rn(raw, TWOPI_D);
        double dlo = __dsub_rn(r, PI_D);
        double q = __dmul_rn(dlo, dlo);
        g_dlo2d[v][lj] = q;
        g_dlo2f[v][lj] = (float)q;
        if (q < blo) { blo = q; bio = lj; }
    }
    __syncthreads();      // g_dlo2f visible to chunk scan below

    // chunk min/max of this vertex's lon table (warps 0..5, one per chunk)
    if (t < 192) {
        int w = t >> 5, lane = t & 31;
        float mn = 1.0e30f, mx = -1.0e30f;
        for (int lj = w * CHW + lane; lj < w * CHW + CHW; lj += 32) {
            float q = g_dlo2f[v][lj];
            mn = fminf(mn, q); mx = fmaxf(mx, q);
        }
#pragma unroll
        for (int off = 16; off > 0; off >>= 1) {
            mn = fminf(mn, __shfl_down_sync(0xFFFFFFFFu, mn, off));
            mx = fmaxf(mx, __shfl_down_sync(0xFFFFFFFFu, mx, off));
        }
        if (lane == 0) { g_cmin[v][w] = mn; g_cmax[v][w] = mx; }
    }

    // separable argmin (lex tie-break == first-index), unchanged
#pragma unroll
    for (int pass = 0; pass < 2; pass++) {
        double bv = pass ? blo : bla;
        int    bi = pass ? bio : bia;
#pragma unroll
        for (int off = 16; off > 0; off >>= 1) {
            double ov = __shfl_down_sync(0xFFFFFFFFu, bv, off);
            int    oi = __shfl_down_sync(0xFFFFFFFFu, bi, off);
            if (ov < bv || (ov == bv && oi < bi)) { bv = ov; bi = oi; }
        }
        if ((t & 31) == 0) { rv[t >> 5] = bv; ri[t >> 5] = bi; }
        __syncthreads();
        if (t < 8) {
            bv = rv[t]; bi = ri[t];
#pragma unroll
            for (int off = 4; off > 0; off >>= 1) {
                double ov = __shfl_down_sync(0xFFu, bv, off);
                int    oi = __shfl_down_sync(0xFFu, bi, off);
                if (ov < bv || (ov == bv && oi < bi)) { bv = ov; bi = oi; }
            }
            if (t == 0) sbest[pass] = bi;
        }
        __syncthreads();
    }
    if (t == 0) g_v2gi[v] = (unsigned)(sbest[0] * WW + sbest[1]);
}

// ---- K1: vmap with per-chunk vertex pruning + packed-key argmin + exact f64 fallback ----
// Pruning safety: bup = min_v fl(sa[v]+cmax[v]) upper-bounds every pixel's winner sum
// (+<=2e-6 rounding). Pruned u has sum >= bup + 2e-4 - 4e-6 > winner + 1e-4 at every
// pixel -> can neither win nor enter the 1e-4 fallback margin. Key masking (16 ulp,
// <=3e-5) only affects decisions with margin < 3e-5 < 1e-4 -> routed to exact fallback.
__global__ void __launch_bounds__(256) k_vmap() {
    __shared__ float sa[NV];
    __shared__ int   slist[NV];
    __shared__ int   scount;
    int t = threadIdx.x;
    int li = blockIdx.y;
    int chunk = blockIdx.x;
    if (t < NV) sa[t] = g_dla2f[t][li];
    __syncthreads();
    if (t == 0) {
        float bup = 1.0e30f;
#pragma unroll
        for (int v = 0; v < NV; v++) bup = fminf(bup, sa[v] + g_cmax[v][chunk]);
        int n = 0;
#pragma unroll
        for (int v = 0; v < NV; v++)
            if (sa[v] + g_cmin[v][chunk] <= bup + 2.0e-4f) slist[n++] = v;
        scount = n;
    }
    __syncthreads();
    if (t >= CHW) return;
    int lj = chunk * CHW + t;
    int n = scount;
    int m1 = 0x7F000000, m2 = 0x7F000000;    // huge positive-float bit pattern
    for (int i = 0; i < n; i++) {            // block-uniform trip count
        int v = slist[i];
        float s = sa[v] + __ldg(&g_dlo2f[v][lj]);
        int key = (__float_as_int(s) & 0xFFFFFFF0) | v;   // d2>0 -> int order == float order
        int nm1 = min(m1, key);
        m2 = min(m2, max(m1, key));
        m1 = nm1;
    }
    int bv = m1 & 15;
    float s1 = __int_as_float(m1 & 0xFFFFFFF0);
    float s2 = __int_as_float(m2 & 0xFFFFFFF0);
    if (s2 - s1 < 1.0e-4f) {   // ambiguous -> exact f64 over ALL 12 (reference semantics)
        double best = 1.0e300; bv = 0;
#pragma unroll
        for (int v = 0; v < NV; v++) {
            double s = __dadd_rn(g_dla2d[v][li], g_dlo2d[v][lj]);
            if (s < best) { best = s; bv = v; }
        }
    }
    int p = li * WW + lj;
    int j = p / HH;             // g2v = reshape(lon,lat).T scramble
    int i = p - j * HH;
    g_vmap[i * WW + j] = (unsigned char)bv;
}

// ---- grid barrier across GNN_BLOCKS co-resident blocks ----
__device__ __forceinline__ void gbar(unsigned target) {
    __syncthreads();
    if (threadIdx.x == 0) {
        __threadfence();
        atomicAdd(&g_bar, 1u);
        while (atomicAdd(&g_bar, 0u) < target) { }
        __threadfence();
    }
    __syncthreads();
}

// ---- K2: persistent fused GNN (unchanged from R11) ----
__global__ void __launch_bounds__(256) k_gnn(const float* __restrict__ x,
                                             const float* __restrict__ Win,
                                             const float* __restrict__ bin,
                                             const float* __restrict__ Wlayers,
                                             const float* __restrict__ bl,
                                             const float* __restrict__ Wout,
                                             const float* __restrict__ bout) {
    int blk = blockIdx.x;
    int b = blk >> 1, half = blk & 1;
    int t = threadIdx.x;
    __shared__ __align__(16) float h_s[NV * DD];
    __shared__ __align__(16) float agg_s[NV * DD];

#pragma unroll
    for (int v = 0; v < NV; v++) {
        unsigned p = g_v2gi[v];
        int pi = p / WW, pj = p - pi * WW;
        const float* xb = x + ((long)(b * CC) * HH + pi) * WW + pj;
        float acc = __ldg(&bin[t]);
        acc = fmaf(__ldg(xb + 0L*HH*WW), __ldg(&Win[0*DD + t]), acc);
        acc = fmaf(__ldg(xb + 1L*HH*WW), __ldg(&Win[1*DD + t]), acc);
        acc = fmaf(__ldg(xb + 2L*HH*WW), __ldg(&Win[2*DD + t]), acc);
        acc = fmaf(__ldg(xb + 3L*HH*WW), __ldg(&Win[3*DD + t]), acc);
        h_s[v * DD + t] = acc;
    }
    __syncthreads();

    int d  = half * 128 + (t & 127);
    int vb = (t >> 7) * 6;
    const float4* a4 = reinterpret_cast<const float4*>(agg_s);

    for (int l = 0; l < 4; l++) {
#pragma unroll
        for (int v = 0; v < NV; v++) {
            float s = h_s[c_nbr[v][0]*DD + t] + h_s[c_nbr[v][1]*DD + t]
                    + h_s[c_nbr[v][2]*DD + t] + h_s[c_nbr[v][3]*DD + t]
                    + h_s[c_nbr[v][4]*DD + t];
            agg_s[v * DD + t] = s * 0.2f;
        }
        __syncthreads();

        const float* Wl = Wlayers + l * DD * DD;
        float acc[6] = {0.f, 0.f, 0.f, 0.f, 0.f, 0.f};
#pragma unroll 4
        for (int kq = 0; kq < DD/4; kq++) {
            float w0 = __ldg(Wl + (kq*4 + 0) * DD + d);
            float w1 = __ldg(Wl + (kq*4 + 1) * DD + d);
            float w2 = __ldg(Wl + (kq*4 + 2) * DD + d);
            float w3 = __ldg(Wl + (kq*4 + 3) * DD + d);
#pragma unroll
            for (int r = 0; r < 6; r++) {
                float4 a = a4[(vb + r) * (DD/4) + kq];
                acc[r] = fmaf(a.x, w0, fmaf(a.y, w1, fmaf(a.z, w2, fmaf(a.w, w3, acc[r]))));
            }
        }
        float bias = __ldg(&bl[l * DD + d]);
#pragma unroll
        for (int r = 0; r < 6; r++) {
            int v = vb + r;
            g_hn[(b * NV + v) * DD + d] = h_s[v * DD + d] + fmaxf(acc[r] + bias, 0.0f);
        }

        gbar((unsigned)(GNN_BLOCKS * (l + 1)));

        float4* h4 = reinterpret_cast<float4*>(h_s);
        const float4* gh4 = reinterpret_cast<const float4*>(g_hn + b * NV * DD);
#pragma unroll
        for (int idx = t; idx < NV * DD / 4; idx += 256) h4[idx] = gh4[idx];
        __syncthreads();
    }

    int w = t >> 5, lane = t & 31;
#pragma unroll
    for (int r = 0; r < 3; r++) {
        int pair = half * 24 + w * 3 + r;
        int v = pair >> 2, c = pair & 3;
        float s = 0.f;
#pragma unroll
        for (int k = lane; k < DD; k += 32)
            s = fmaf(h_s[v * DD + k], __ldg(&Wout[k * CC + c]), s);
#pragma unroll
        for (int off = 16; off > 0; off >>= 1)
            s += __shfl_down_sync(0xFFFFFFFFu, s, off);
        if (lane == 0) g_nodes[(b * NV + v) * CC + c] = s + __ldg(&bout[c]);
    }
}

// ---- K3: output scatter — streaming stores, one block serves all 4 c-planes ----
__global__ void __launch_bounds__(256) k_scatter(float* __restrict__ out) {
    int b = blockIdx.y;
    __shared__ float sval[NV][CC];
    if (threadIdx.x < NV * CC)
        sval[threadIdx.x >> 2][threadIdx.x & 3] = g_nodes[b * NV * CC + threadIdx.x];
    __syncthreads();
    float4* out4 = reinterpret_cast<float4*>(out);
    const uchar4* vmap4 = reinterpret_cast<const uchar4*>(g_vmap);
    int q0 = blockIdx.x * 512 + threadIdx.x;
#pragma unroll
    for (int r = 0; r < 2; r++) {
        int q = q0 + r * 256;
        if (q < NQ4) {
            uchar4 vm = vmap4[q];
#pragma unroll
            for (int c = 0; c < CC; c++) {
                float4 o;
                o.x = sval[vm.x][c]; o.y = sval[vm.y][c];
                o.z = sval[vm.z][c]; o.w = sval[vm.w][c];
                __stcs(&out4[(long)(b * CC + c) * NQ4 + q], o);
            }
        }
    }
}

extern "C" void kernel_launch(void* const* d_in, const int* in_sizes, int n_in,
                              void* d_out, int out_size) {
    const float* x        = (const float*)d_in[0];
    const float* W_in     = (const float*)d_in[2];
    const float* b_in     = (const float*)d_in[3];
    const float* W_layers = (const float*)d_in[4];
    const float* b_layers = (const float*)d_in[5];
    const float* W_out    = (const float*)d_in[6];
    const float* b_out    = (const float*)d_in[7];
    float* out = (float*)d_out;

    k_prep<<<NV, 256>>>();
    k_vmap<<<dim3(NCHUNK, HH), 256>>>();
    k_gnn<<<GNN_BLOCKS, 256>>>(x, W_in, b_in, W_layers, b_layers, W_out, b_out);
    k_scatter<<<dim3((NQ4 + 511) / 512, BB), 256>>>(out);
}

// round 13
// speedup vs baseline: 1.2751x; 1.2751x over previous
#include <cuda_runtime.h>
#include <stdint.h>

#define HH 721
#define WW 1440
#define NPTS (HH*WW)
#define NQ4  (NPTS/4)
#define BB 16
#define CC 4
#define DD 256
#define NV 12
#define MEGA_BLOCKS 148
#define GNN_BLOCKS 32
#define PI_D 3.141592653589793
#define TWOPI_D (2.0*PI_D)

static __device__ double        g_dla2d[NV][HH];
static __device__ double        g_dlo2d[NV][WW];
static __device__ float         g_dla2f[NV][HH];
static __device__ float         g_dlo2f[NV][WW];
static __device__ unsigned int  g_v2gi[NV];
static __device__ unsigned char g_vmap[NPTS];
static __device__ float         g_nodes[BB*NV*CC];
static __device__ float         g_hn[BB*NV*DD];
static __device__ volatile unsigned g_bar  = 0;   // full-grid barrier counter
static __device__ volatile unsigned g_bar2 = 0;   // GNN 32-block sub-barrier counter

__constant__ signed char c_vcode[NV][3] = {
    {-1,2,0},{1,2,0},{-1,-2,0},{1,-2,0},{0,-1,2},{0,1,2},
    {0,-1,-2},{0,1,-2},{2,0,-1},{2,0,1},{-2,0,-1},{-2,0,1}};
__constant__ int c_nbr[NV][5] = {
    {11,5,1,7,10},{0,5,7,9,8},{11,10,3,4,6},{9,4,2,6,8},
    {5,11,3,9,2},{0,11,1,9,4},{10,7,3,2,8},{0,1,10,6,8},
    {7,1,3,6,9},{1,5,3,4,8},{0,7,11,2,6},{0,5,10,2,4}};

// ---- spin barriers (counters reset by k_scatter each iteration; stream-ordered) ----
__device__ __forceinline__ void barrier_all() {
    __syncthreads();
    if (threadIdx.x == 0) {
        __threadfence();
        atomicAdd((unsigned*)&g_bar, 1u);
        while (g_bar < (unsigned)MEGA_BLOCKS) { }
        __threadfence();
    }
    __syncthreads();
}
__device__ __forceinline__ void barrier_gnn(unsigned target) {
    __syncthreads();
    if (threadIdx.x == 0) {
        __threadfence();
        atomicAdd((unsigned*)&g_bar2, 1u);
        while (g_bar2 < target) { }
        __threadfence();
    }
    __syncthreads();
}

// ---- K0: mega kernel. P1: blocks 0-11 build f64 tables + v2g. barrier.
//          P2: blocks 0-31 run the whole GNN; blocks 32-147 run vmap rows (overlapped). ----
__global__ void __launch_bounds__(256) k_mega(const float* __restrict__ x,
                                              const float* __restrict__ Win,
                                              const float* __restrict__ bin,
                                              const float* __restrict__ Wlayers,
                                              const float* __restrict__ bl,
                                              const float* __restrict__ Wout,
                                              const float* __restrict__ bout) {
    int bid = blockIdx.x, t = threadIdx.x;
    __shared__ __align__(16) float h_s[NV * DD];
    __shared__ __align__(16) float agg_s[NV * DD];
    __shared__ double s_vll[2];
    __shared__ double s_rv[8];
    __shared__ int    s_ri[8];
    __shared__ int    s_best[2];

    // ================= P1: per-vertex f64 tables + separable argmin =================
    if (bid < NV) {
        int v = bid;
        if (t == 0) {
            float phi = (float)((1.0 + sqrt(5.0)) * 0.5);
            float c[3];
#pragma unroll
            for (int k = 0; k < 3; k++) {
                int cd = c_vcode[v][k];
                float m = (cd == 2 || cd == -2) ? phi : 1.0f;
                c[k] = (cd == 0) ? 0.0f : (cd < 0 ? -m : m);
            }
            float n2 = __fadd_rn(__fadd_rn(__fmul_rn(c[0],c[0]), __fmul_rn(c[1],c[1])),
                                 __fmul_rn(c[2],c[2]));
            float nrm = __fsqrt_rn(n2);
            float xx = __fdiv_rn(c[0],nrm), yy = __fdiv_rn(c[1],nrm), zz = __fdiv_rn(c[2],nrm);
            float s = __fsqrt_rn(__fsub_rn(1.0f, __fmul_rn(zz,zz)));
            s_vll[0] = (double)__fmul_rn(2.0f, atan2f(zz, __fadd_rn(1.0f, s)));  // XLA asin
            s_vll[1] = (double)atan2f(yy, xx);
        }
        __syncthreads();
        double vlat = s_vll[0], vlon = s_vll[1];

        double bla = 1.0e300, blo = 1.0e300; int bia = 0, bio = 0;
        double dla_s = __ddiv_rn(PI_D, 720.0);
        double dlo_s = __ddiv_rn(TWOPI_D, 1439.0);
        for (int li = t; li < HH; li += 256) {
            double lat = __dadd_rn(-(PI_D*0.5), __dmul_rn((double)li, dla_s));
            if (li == 360) lat = 1.0e-12;        // symmetry row pinned positive (validated)
            double dla = __dsub_rn(lat, vlat);
            double q = __dmul_rn(dla, dla);
            g_dla2d[v][li] = q;
            g_dla2f[v][li] = (float)q;
            if (q < bla) { bla = q; bia = li; }
        }
        for (int lj = t; lj < WW; lj += 256) {
            double lon = __dadd_rn(-PI_D, __dmul_rn((double)lj, dlo_s));
            double raw = __dadd_rn(__dsub_rn(lon, vlon), PI_D);
            double r = raw;
            if (raw >= TWOPI_D)   r = __dsub_rn(raw, TWOPI_D);
            else if (raw < 0.0)   r = __dadd_rn(raw, TWOPI_D);
            double dlo = __dsub_rn(r, PI_D);
            double q = __dmul_rn(dlo, dlo);
            g_dlo2d[v][lj] = q;
            g_dlo2f[v][lj] = (float)q;
            if (q < blo) { blo = q; bio = lj; }
        }
#pragma unroll
        for (int pass = 0; pass < 2; pass++) {
            double bv = pass ? blo : bla;
            int    bi = pass ? bio : bia;
#pragma unroll
            for (int off = 16; off > 0; off >>= 1) {
                double ov = __shfl_down_sync(0xFFFFFFFFu, bv, off);
                int    oi = __shfl_down_sync(0xFFFFFFFFu, bi, off);
                if (ov < bv || (ov == bv && oi < bi)) { bv = ov; bi = oi; }
            }
            if ((t & 31) == 0) { s_rv[t >> 5] = bv; s_ri[t >> 5] = bi; }
            __syncthreads();
            if (t < 8) {
                bv = s_rv[t]; bi = s_ri[t];
#pragma unroll
                for (int off = 4; off > 0; off >>= 1) {
                    double ov = __shfl_down_sync(0xFFu, bv, off);
                    int    oi = __shfl_down_sync(0xFFu, bi, off);
                    if (ov < bv || (ov == bv && oi < bi)) { bv = ov; bi = oi; }
                }
                if (t == 0) s_best[pass] = bi;
            }
            __syncthreads();
        }
        if (t == 0) g_v2gi[v] = (unsigned)(s_best[0] * WW + s_best[1]);
    }

    barrier_all();     // tables + v2g visible to everyone

    if (bid < GNN_BLOCKS) {
        // ================= P2a: fused GNN (identical math to R11/R12) =================
        int b = bid >> 1, half = bid & 1;

        // inproj: full h0 per block
#pragma unroll
        for (int v = 0; v < NV; v++) {
            unsigned p = g_v2gi[v];
            int pi = p / WW, pj = p - pi * WW;
            const float* xb = x + ((long)(b * CC) * HH + pi) * WW + pj;
            float acc = __ldg(&bin[t]);
            acc = fmaf(__ldg(xb + 0L*HH*WW), __ldg(&Win[0*DD + t]), acc);
            acc = fmaf(__ldg(xb + 1L*HH*WW), __ldg(&Win[1*DD + t]), acc);
            acc = fmaf(__ldg(xb + 2L*HH*WW), __ldg(&Win[2*DD + t]), acc);
            acc = fmaf(__ldg(xb + 3L*HH*WW), __ldg(&Win[3*DD + t]), acc);
            h_s[v * DD + t] = acc;
        }
        __syncthreads();

        int d  = half * 128 + (t & 127);
        int vb = (t >> 7) * 6;
        const float4* a4 = reinterpret_cast<const float4*>(agg_s);

        for (int l = 0; l < 4; l++) {
#pragma unroll
            for (int v = 0; v < NV; v++) {
                float s = h_s[c_nbr[v][0]*DD + t] + h_s[c_nbr[v][1]*DD + t]
                        + h_s[c_nbr[v][2]*DD + t] + h_s[c_nbr[v][3]*DD + t]
                        + h_s[c_nbr[v][4]*DD + t];
                agg_s[v * DD + t] = s * 0.2f;
            }
            __syncthreads();

            const float* Wl = Wlayers + l * DD * DD;
            float acc[6] = {0.f, 0.f, 0.f, 0.f, 0.f, 0.f};
#pragma unroll 4
            for (int kq = 0; kq < DD/4; kq++) {
                float w0 = __ldg(Wl + (kq*4 + 0) * DD + d);
                float w1 = __ldg(Wl + (kq*4 + 1) * DD + d);
                float w2 = __ldg(Wl + (kq*4 + 2) * DD + d);
                float w3 = __ldg(Wl + (kq*4 + 3) * DD + d);
#pragma unroll
                for (int r = 0; r < 6; r++) {
                    float4 a = a4[(vb + r) * (DD/4) + kq];
                    acc[r] = fmaf(a.x, w0, fmaf(a.y, w1, fmaf(a.z, w2, fmaf(a.w, w3, acc[r]))));
                }
            }
            float bias = __ldg(&bl[l * DD + d]);
#pragma unroll
            for (int r = 0; r < 6; r++) {
                int v = vb + r;
                g_hn[(b * NV + v) * DD + d] = h_s[v * DD + d] + fmaxf(acc[r] + bias, 0.0f);
            }

            barrier_gnn((unsigned)(GNN_BLOCKS * (l + 1)));

            float4* h4 = reinterpret_cast<float4*>(h_s);
            const float4* gh4 = reinterpret_cast<const float4*>(g_hn + b * NV * DD);
#pragma unroll
            for (int idx = t; idx < NV * DD / 4; idx += 256) h4[idx] = gh4[idx];
            __syncthreads();
        }

        // outproj: 48 (v,c) pairs split between the two halves
        int w = t >> 5, lane = t & 31;
#pragma unroll
        for (int r = 0; r < 3; r++) {
            int pair = half * 24 + w * 3 + r;
            int v = pair >> 2, c = pair & 3;
            float s = 0.f;
#pragma unroll
            for (int k = lane; k < DD; k += 32)
                s = fmaf(h_s[v * DD + k], __ldg(&Wout[k * CC + c]), s);
#pragma unroll
            for (int off = 16; off > 0; off >>= 1)
                s += __shfl_down_sync(0xFFFFFFFFu, s, off);
            if (lane == 0) g_nodes[(b * NV + v) * CC + c] = s + __ldg(&bout[c]);
        }
    } else {
        // ================= P2b: vmap rows (overlapped with GNN) =================
        const int nb = MEGA_BLOCKS - GNN_BLOCKS;      // 116 blocks
        for (int li = bid - GNN_BLOCKS; li < HH; li += nb) {
            float sa[NV];
#pragma unroll
            for (int v = 0; v < NV; v++) sa[v] = __ldg(&g_dla2f[v][li]);
            for (int lj = t; lj < WW; lj += 256) {
                // packed-key argmin: d2>0 -> int order == float order; 16-ulp mask (<=3e-5)
                // perturbs only margins < 1e-4 which are routed to the exact fallback.
                int m1 = 0x7F000000, m2 = 0x7F000000;
#pragma unroll
                for (int v = 0; v < NV; v++) {
                    float s = sa[v] + __ldg(&g_dlo2f[v][lj]);
                    int key = (__float_as_int(s) & 0xFFFFFFF0) | v;
                    int nm1 = min(m1, key);
                    m2 = min(m2, max(m1, key));
                    m1 = nm1;
                }
                int bv = m1 & 15;
                float s1 = __int_as_float(m1 & 0xFFFFFFF0);
                float s2 = __int_as_float(m2 & 0xFFFFFFF0);
                if (s2 - s1 < 1.0e-4f) {   // ambiguous -> exact f64 reference compare
                    double best = 1.0e300; bv = 0;
#pragma unroll
                    for (int v = 0; v < NV; v++) {
                        double s = __dadd_rn(g_dla2d[v][li], g_dlo2d[v][lj]);
                        if (s < best) { best = s; bv = v; }
                    }
                }
                int p = li * WW + lj;
                int j = p / HH;             // g2v = reshape(lon,lat).T scramble
                int i = p - j * HH;
                g_vmap[i * WW + j] = (unsigned char)bv;
            }
        }
    }
}

// ---- K1: output scatter (unchanged, measured at write roofline) + counter reset ----
__global__ void __launch_bounds__(256) k_scatter(float* __restrict__ out) {
    if (blockIdx.x == 0 && blockIdx.y == 0 && threadIdx.x == 0) { g_bar = 0; g_bar2 = 0; }
    int b = blockIdx.y;
    __shared__ float sval[NV][CC];
    if (threadIdx.x < NV * CC)
        sval[threadIdx.x >> 2][threadIdx.x & 3] = g_nodes[b * NV * CC + threadIdx.x];
    __syncthreads();
    float4* out4 = reinterpret_cast<float4*>(out);
    const uchar4* vmap4 = reinterpret_cast<const uchar4*>(g_vmap);
    int q0 = blockIdx.x * 512 + threadIdx.x;
#pragma unroll
    for (int r = 0; r < 2; r++) {
        int q = q0 + r * 256;
        if (q < NQ4) {
            uchar4 vm = vmap4[q];
#pragma unroll
            for (int c = 0; c < CC; c++) {
                float4 o;
                o.x = sval[vm.x][c]; o.y = sval[vm.y][c];
                o.z = sval[vm.z][c]; o.w = sval[vm.w][c];
                __stcs(&out4[(long)(b * CC + c) * NQ4 + q], o);
            }
        }
    }
}

extern "C" void kernel_launch(void* const* d_in, const int* in_sizes, int n_in,
                              void* d_out, int out_size) {
    const float* x        = (const float*)d_in[0];
    const float* W_in     = (const float*)d_in[2];
    const float* b_in     = (const float*)d_in[3];
    const float* W_layers = (const float*)d_in[4];
    const float* b_layers = (const float*)d_in[5];
    const float* W_out    = (const float*)d_in[6];
    const float* b_out    = (const float*)d_in[7];
    float* out = (float*)d_out;

    k_mega<<<MEGA_BLOCKS, 256>>>(x, W_in, b_in, W_layers, b_layers, W_out, b_out);
    k_scatter<<<dim3((NQ4 + 511) / 512, BB), 256>>>(out);
}